// round 13
// baseline (speedup 1.0000x reference)
#include <cuda_runtime.h>
#include <math.h>

#define BATCH 512
#define LEN   50
#define EMB   512
#define C1    20
#define C2    40
#define EPSV  1e-5f
#define NG    4                           // K split factor (128 j per part)

// ---------------- device scratch ----------------
__device__ float  g_A   [2*BATCH*C2*23];  // [side][b][o][x]
__device__ float  g_bn2 [2*C2];           // scale | shift
__device__ float  g_weff[4840];           // Wfc2 @ Wfc1
__device__ float  g_bias0;
__device__ float  g_fp  [NG*2*BATCH*1000];// split-K partials [G][side][b][t*20+c]
__device__ double g_accS[C2];             // BN2 sum accumulators (zero-init)
__device__ double g_accQ[C2];
__device__ int    g_cntS[BATCH];          // per-sample split-K arrival counters
__device__ int    g_cntE;                 // epilogue arrival counter

__device__ __forceinline__ void ffma2(unsigned long long& d,
                                      unsigned long long a, unsigned long long b) {
    asm("fma.rn.f32x2 %0, %1, %2, %0;" : "+l"(d) : "l"(a), "l"(b));
}
__device__ __forceinline__ unsigned smem_u32(const void* p) {
    return (unsigned)__cvta_generic_to_shared(p);
}
__device__ __forceinline__ void bulk_g2s(unsigned dst, const void* src,
                                         unsigned bytes, unsigned bar) {
    asm volatile(
        "cp.async.bulk.shared::cta.global.mbarrier::complete_tx::bytes "
        "[%0], [%1], %2, [%3];"
        :: "r"(dst), "l"(src), "r"(bytes), "r"(bar) : "memory");
}
#define MBAR_INIT(addr, cnt) \
    asm volatile("mbarrier.init.shared.b64 [%0], %1;" :: "r"(addr), "r"(cnt) : "memory")
#define MBAR_EXPECT_TX(addr, bytes) \
    asm volatile("mbarrier.arrive.expect_tx.shared.b64 _, [%0], %1;" \
                 :: "r"(addr), "r"(bytes) : "memory")
#define MBAR_WAIT(addr, parity) do {                                        \
    asm volatile(                                                           \
        "{\n\t.reg .pred P1;\n\t"                                           \
        "WAIT_LOOP_%=:\n\t"                                                 \
        "mbarrier.try_wait.parity.acquire.cta.shared::cta.b64 P1, [%0], %1, 0x989680;\n\t" \
        "@P1 bra.uni WAIT_DONE_%=;\n\t"                                     \
        "bra.uni WAIT_LOOP_%=;\n\t"                                         \
        "WAIT_DONE_%=:\n\t}"                                                \
        :: "r"(addr), "r"(parity) : "memory");                              \
} while (0)

// kS smem: rows padded to 528B (verified conflict behavior)
#define S_OFF_ES  0                       // 100 rows x 528B = 52800
#define S_OFF_WS  52800                   //  20 rows x 528B = 10560
#define S_OFF_BAR 63360                   // mbarrier (8B)
#define SMEM_KS   63392
// epilogue overlay inside es (dead after GEMM):
#define E_FS   0                          // float fs[2][1050]  = 8400B
#define E_WXY  8400                       // float wxy[2][2400] = 19200B
#define E_M    27600                      // float m[2][500]    = 4000B
#define E_BN   31600                      // float bn[2][2][20] = 320B
#define E_SQ   31920                      // float shs[80], shq[80] = 640B

// ---------------------------------------------------------------------------
// kS: split-K GEMM + fused weight precompute + fused epilogue + fused stats.
// block = (b, G). 128 thr, 3 blocks/SM, grid (512, 4).
// ---------------------------------------------------------------------------
__global__ __launch_bounds__(128, 3)
void kS(const int* __restrict__ src, const int* __restrict__ trg,
        const float* __restrict__ emb_src, const float* __restrict__ emb_trg,
        const float* __restrict__ W1, const float* __restrict__ g1,
        const float* __restrict__ beta1, const float* __restrict__ W2,
        const float* __restrict__ g2, const float* __restrict__ beta2,
        const float* __restrict__ Wfc1, const float* __restrict__ Wfc2,
        const float* __restrict__ bfc1, const float* __restrict__ bfc2)
{
    extern __shared__ char smraw[];
    float* esf = (float*)(smraw + S_OFF_ES);
    __shared__ int sflag, sflag2;

    const int tid = threadIdx.x;
    const int b   = blockIdx.x;
    const int G   = blockIdx.y;            // K quarter: j in [G*128, G*128+128)

    const unsigned bar  = smem_u32(smraw + S_OFF_BAR);
    const unsigned es_u = smem_u32(smraw + S_OFF_ES);
    const unsigned ws_u = smem_u32(smraw + S_OFF_WS);

    if (tid == 0) MBAR_INIT(bar, 1);
    __syncthreads();
    if (tid == 0) MBAR_EXPECT_TX(bar, 120u*512u);
    __syncthreads();

    if (tid < 100) {                       // one bulk copy per token row
        int tv = (tid < 50) ? src[b*LEN + tid] : trg[b*LEN + (tid - 50)];
        const float* etab = (tid < 50) ? emb_src : emb_trg;
        bulk_g2s(es_u + (unsigned)tid*528u,
                 etab + (size_t)tv*EMB + G*128, 512u, bar);
    } else if (tid < 120) {                // W1 rows (row-major, padded stride)
        int c = tid - 100;
        bulk_g2s(ws_u + (unsigned)c*528u,
                 W1 + (size_t)c*EMB + G*128, 512u, bar);
    }

    // fused k0: weff/bias0 computed while TMA is in flight (G==3 blocks)
    if (G == 3) {
        if (tid < 10) {
            int k = b*10 + tid;
            if (k < 4840) {
                float w = 0.f;
#pragma unroll
                for (int c = 0; c < 20; c++) w += Wfc2[c]*Wfc1[c*4840 + k];
                g_weff[k] = w;
            }
        } else if (tid == 10 && b == 0) {
            float z = bfc2[0];
#pragma unroll
            for (int c = 0; c < 20; c++) z += Wfc2[c]*bfc1[c];
            g_bias0 = z;
        }
    }

    MBAR_WAIT(bar, 0);

    // GEMM: thread = (token-pair tpg, channel-half ch) — verified R11 tile
    const int ch  = tid & 1;
    const int tpg = tid >> 1;
    const bool active = (tpg < 50);
    const int side = (tpg >= 25);
    const int tp   = tpg - side*25;
    const int r1   = tpg + side*25;
    const int r2   = r1 + 25;

    unsigned long long acc2[20];
#pragma unroll
    for (int i = 0; i < 20; i++) acc2[i] = 0ULL;

    if (active) {
        const float4* e1 = (const float4*)esf + r1*33;
        const float4* e2 = (const float4*)esf + r2*33;
        const float4* wf = (const float4*)(smraw + S_OFF_WS);
#pragma unroll
        for (int j4 = 0; j4 < 32; j4++) {
            float4 ea = e1[j4], eb = e2[j4];
            ulonglong2 eva = *reinterpret_cast<ulonglong2*>(&ea);
            ulonglong2 evb = *reinterpret_cast<ulonglong2*>(&eb);
#pragma unroll
            for (int ci = 0; ci < 10; ci++) {
                float4 w = wf[(ch*10 + ci)*33 + j4];
                ulonglong2 wv = *reinterpret_cast<ulonglong2*>(&w);
                ffma2(acc2[ci],      eva.x, wv.x);
                ffma2(acc2[ci],      eva.y, wv.y);
                ffma2(acc2[10 + ci], evb.x, wv.x);
                ffma2(acc2[10 + ci], evb.y, wv.y);
            }
        }
        float* base = &g_fp[((size_t)((G*2 + side)*512 + b))*1000];
        float* d1 = base + tp*20        + ch*10;
        float* d2 = base + (tp + 25)*20 + ch*10;
#pragma unroll
        for (int ci = 0; ci < 10; ci++) {
            unsigned long long v = acc2[ci];
            d1[ci] = __uint_as_float((unsigned)v) + __uint_as_float((unsigned)(v >> 32));
            unsigned long long u = acc2[10 + ci];
            d2[ci] = __uint_as_float((unsigned)u) + __uint_as_float((unsigned)(u >> 32));
        }
    }

    // -------- fused kE: last of the 4 G-blocks for this b runs the epilogue
    if (tid == 0) {
        __threadfence();
        int old = atomicAdd(&g_cntS[b], 1);
        sflag = (old == NG - 1);
    }
    __syncthreads();
    if (!sflag) return;

    {
        float* fs  = (float*)(smraw + E_FS);
        float* wxy = (float*)(smraw + E_WXY);
        float* m   = (float*)(smraw + E_M);
        float* bn  = (float*)(smraw + E_BN);
        float* shs = (float*)(smraw + E_SQ);        // [2][40]
        float* shq = shs + 80;

        __threadfence();                             // see all partials

        // sum the 4 split-K partials, both sides
        for (int q = tid; q < 2000; q += 128) {
            int u = q / 1000, r = q - u*1000;
            float v = 0.f;
#pragma unroll
            for (int g = 0; g < NG; g++)
                v += g_fp[((size_t)((g*2 + u)*512 + b))*1000 + r];
            int t = r / 20, c = r - t*20;
            fs[u*1050 + t*21 + c] = v;
        }
        // wxy from W2 (was k0)
        for (int q = tid; q < 4800; q += 128) {
            int sside = q / 2400, r = q % 2400;
            int o = r / 60, rc = r % 60, c = rc / 3, d = rc % 3;
            const float* w = W2 + (o*20 + c)*9;
            wxy[q] = sside ? (w[d*3+0] + w[d*3+1] + w[d*3+2])
                           : (w[0*3+d] + w[1*3+d] + w[2*3+d]);
        }
        __syncthreads();

        // BN1 stats per (side, channel)
        if (tid < 40) {
            int u = tid / 20, c = tid - u*20;
            float s = 0.f, s2 = 0.f;
#pragma unroll 10
            for (int l = 0; l < 50; l++) {
                float v = fs[u*1050 + l*21 + c];
                s += v; s2 += v*v;
            }
            float mu  = s * (1.f/50.f);
            float var = s2 * (1.f/50.f) - mu*mu;
            float sc  = g1[c] * rsqrtf(var + EPSV);
            bn[u*20 + c]      = sc;
            bn[40 + u*20 + c] = beta1[c] - mu*sc;
        }
        __syncthreads();

        // BN1 apply + relu + pool1
        for (int q = tid; q < 1000; q += 128) {
            int u = q / 500, r = q - u*500;
            int c = r / 25, x = r - c*25;
            float sc = bn[u*20 + c], sh = bn[40 + u*20 + c];
            float a0 = fs[u*1050 + (2*x    )*21 + c]*sc + sh;
            float a1 = fs[u*1050 + (2*x + 1)*21 + c]*sc + sh;
            m[u*500 + c*25 + x] = fmaxf(fmaxf(a0, a1), 0.f);
        }
        __syncthreads();

        // conv1d, both sides in parallel (80 threads), sums -> smem
        if (tid < 80) {
            int u = tid / 40, o = tid - u*40;
            const float* wb = wxy + u*2400 + o*60;
            const float* mu_ = m + u*500;
            float acc[23];
#pragma unroll
            for (int x = 0; x < 23; x++) acc[x] = 0.f;
#pragma unroll
            for (int c = 0; c < 20; c++) {
                float w0 = wb[c*3], w1 = wb[c*3+1], w2 = wb[c*3+2];
                const float* mm = mu_ + c*25;
#pragma unroll
                for (int x = 0; x < 23; x++)
                    acc[x] += w0*mm[x] + w1*mm[x+1] + w2*mm[x+2];
            }
            float s = 0.f, s2 = 0.f;
            float* dst = &g_A[(size_t)(u*BATCH + b)*920 + o*23];
#pragma unroll
            for (int x = 0; x < 23; x++) {
                float v = acc[x];
                dst[x] = v; s += v; s2 += v*v;
            }
            shs[u*40 + o] = s;
            shq[u*40 + o] = s2;
        }
        __syncthreads();

        // fused k3 accumulation: per-o BN2 contributions via f64 reductions
        if (tid < 40) {
            double sA = shs[tid],      sB = shs[40 + tid];
            double qA = shq[tid],      qB = shq[40 + tid];
            atomicAdd(&g_accS[tid], 23.0*(sA + sB));
            atomicAdd(&g_accQ[tid], 23.0*qA + 23.0*qB + 2.0*sA*sB);
        }
    }

    // -------- fused k3 finalize: last of the 512 epilogue blocks
    if (tid == 0) {
        g_cntS[b] = 0;                    // reset for next replay
        __threadfence();
        int old2 = atomicAdd(&g_cntE, 1);
        sflag2 = (old2 == BATCH - 1);
    }
    __syncthreads();
    if (!sflag2) return;

    __threadfence();
    if (tid < 40) {
        double N    = (double)BATCH * 529.0;
        double mean = g_accS[tid] / N;
        double var  = g_accQ[tid] / N - mean*mean;
        float  sc   = g2[tid] * (float)(1.0 / sqrt(var + (double)EPSV));
        g_bn2[tid]      = sc;
        g_bn2[C2 + tid] = beta2[tid] - (float)mean * sc;
        g_accS[tid] = 0.0;                // reset for next replay
        g_accQ[tid] = 0.0;
    }
    if (tid == 0) g_cntE = 0;
}

// ---------------------------------------------------------------------------
// kF: BN2 apply + pool2 + relu + dot(weff) + sigmoid (verified)
// ---------------------------------------------------------------------------
__global__ __launch_bounds__(256)
void kF(float* __restrict__ out)
{
    __shared__ float ua[440], vb[440], sh_s[40], red[8];
    const int b = blockIdx.x, tid = threadIdx.x;

    for (int q = tid; q < 880; q += 256) {
        int half = (q >= 440);
        int r = q - half*440;
        int o = r / 11, xx = r - o*11;
        float sc = g_bn2[o];
        const float* p = &g_A[(size_t)(half*BATCH + b)*920 + o*23];
        (half ? vb : ua)[r] = fmaxf(sc*p[2*xx], sc*p[2*xx+1]);
    }
    if (tid < 40) sh_s[tid] = g_bn2[C2 + tid];
    __syncthreads();

    float part = 0.f;
    if (tid < 242) {
        const int half = (tid >= 121);
        const int r  = tid - half*121;
        const int yy = r / 11, xx = r - yy*11;
#pragma unroll
        for (int oo = 0; oo < 20; oo++) {
            int o = 2*oo + half;
            part += g_weff[o*121 + r] *
                    fmaxf(ua[o*11 + xx] + vb[o*11 + yy] + sh_s[o], 0.f);
        }
    }
#pragma unroll
    for (int off = 16; off > 0; off >>= 1)
        part += __shfl_down_sync(0xffffffffu, part, off);
    if ((tid & 31) == 0) red[tid >> 5] = part;
    __syncthreads();
    if (tid == 0) {
        float s = 0.f;
#pragma unroll
        for (int w = 0; w < 8; w++) s += red[w];
        out[b] = 1.f / (1.f + expf(-(s + g_bias0)));
    }
}

// ---------------------------------------------------------------------------
extern "C" void kernel_launch(void* const* d_in, const int* in_sizes, int n_in,
                              void* d_out, int out_size)
{
    const int*   src     = (const int*)  d_in[0];
    const int*   trg     = (const int*)  d_in[1];
    const float* emb_src = (const float*)d_in[3];
    const float* emb_trg = (const float*)d_in[4];
    const float* W1      = (const float*)d_in[5];
    const float* g1      = (const float*)d_in[7];
    const float* beta1   = (const float*)d_in[8];
    const float* W2      = (const float*)d_in[9];
    const float* g2      = (const float*)d_in[11];
    const float* beta2   = (const float*)d_in[12];
    const float* Wfc1    = (const float*)d_in[13];
    const float* bfc1    = (const float*)d_in[14];
    const float* Wfc2    = (const float*)d_in[15];
    const float* bfc2    = (const float*)d_in[16];

    cudaFuncSetAttribute(kS, cudaFuncAttributeMaxDynamicSharedMemorySize, SMEM_KS);

    kS<<<dim3(BATCH, NG), 128, SMEM_KS>>>(src, trg, emb_src, emb_trg, W1,
                                          g1, beta1, W2, g2, beta2,
                                          Wfc1, Wfc2, bfc1, bfc2);
    kF<<<BATCH, 256>>>((float*)d_out);
}

// round 14
// speedup vs baseline: 1.1582x; 1.1582x over previous
#include <cuda_runtime.h>
#include <math.h>

#define BATCH 512
#define LEN   50
#define EMB   512
#define C1    20
#define C2    40
#define EPSV  1e-5f
#define NG    4                           // K split factor (128 j per part)

// ---------------- device scratch ----------------
__device__ float  g_A   [2*BATCH*C2*23];  // [side][b][o][x]
__device__ float  g_weff[4840];           // Wfc2 @ Wfc1
__device__ float  g_bias0;
__device__ float  g_Wxy [2*C2*C1*3];      // Wx | Wy
__device__ float  g_fp  [NG*2*BATCH*1000];// split-K partials [G][side][b][t*20+c]
__device__ double g_accS[C2];             // BN2 accumulators (zeroed by kS)
__device__ double g_accQ[C2];

__device__ __forceinline__ void ffma2(unsigned long long& d,
                                      unsigned long long a, unsigned long long b) {
    asm("fma.rn.f32x2 %0, %1, %2, %0;" : "+l"(d) : "l"(a), "l"(b));
}
__device__ __forceinline__ unsigned smem_u32(const void* p) {
    return (unsigned)__cvta_generic_to_shared(p);
}
__device__ __forceinline__ void bulk_g2s(unsigned dst, const void* src,
                                         unsigned bytes, unsigned bar) {
    asm volatile(
        "cp.async.bulk.shared::cta.global.mbarrier::complete_tx::bytes "
        "[%0], [%1], %2, [%3];"
        :: "r"(dst), "l"(src), "r"(bytes), "r"(bar) : "memory");
}
#define MBAR_INIT(addr, cnt) \
    asm volatile("mbarrier.init.shared.b64 [%0], %1;" :: "r"(addr), "r"(cnt) : "memory")
#define MBAR_EXPECT_TX(addr, bytes) \
    asm volatile("mbarrier.arrive.expect_tx.shared.b64 _, [%0], %1;" \
                 :: "r"(addr), "r"(bytes) : "memory")
#define MBAR_WAIT(addr, parity) do {                                        \
    asm volatile(                                                           \
        "{\n\t.reg .pred P1;\n\t"                                           \
        "WAIT_LOOP_%=:\n\t"                                                 \
        "mbarrier.try_wait.parity.acquire.cta.shared::cta.b64 P1, [%0], %1, 0x989680;\n\t" \
        "@P1 bra.uni WAIT_DONE_%=;\n\t"                                     \
        "bra.uni WAIT_LOOP_%=;\n\t"                                         \
        "WAIT_DONE_%=:\n\t}"                                                \
        :: "r"(addr), "r"(parity) : "memory");                              \
} while (0)

// kS smem: rows padded to 528B (verified conflict behavior)
#define S_OFF_ES  0                       // 100 rows x 528B = 52800
#define S_OFF_WS  52800                   //  20 rows x 528B = 10560
#define S_OFF_BAR 63360                   // mbarrier (8B)
#define SMEM_KS   63392

// ---------------------------------------------------------------------------
// kS: split-K GEMM (R11-verified) + weight precomputes folded into TMA flight
// block = (b, G). 128 thr, 3 blocks/SM, grid (512, 4).
// ---------------------------------------------------------------------------
__global__ __launch_bounds__(128, 3)
void kS(const int* __restrict__ src, const int* __restrict__ trg,
        const float* __restrict__ emb_src, const float* __restrict__ emb_trg,
        const float* __restrict__ W1, const float* __restrict__ W2,
        const float* __restrict__ Wfc1, const float* __restrict__ Wfc2,
        const float* __restrict__ bfc1, const float* __restrict__ bfc2)
{
    extern __shared__ char smraw[];
    float* esf = (float*)(smraw + S_OFF_ES);

    const int tid = threadIdx.x;
    const int b   = blockIdx.x;
    const int G   = blockIdx.y;            // K quarter: j in [G*128, G*128+128)

    const unsigned bar  = smem_u32(smraw + S_OFF_BAR);
    const unsigned es_u = smem_u32(smraw + S_OFF_ES);
    const unsigned ws_u = smem_u32(smraw + S_OFF_WS);

    if (tid == 0) MBAR_INIT(bar, 1);
    __syncthreads();
    if (tid == 0) MBAR_EXPECT_TX(bar, 120u*512u);
    __syncthreads();

    if (tid < 100) {                       // one bulk copy per token row
        int tv = (tid < 50) ? src[b*LEN + tid] : trg[b*LEN + (tid - 50)];
        const float* etab = (tid < 50) ? emb_src : emb_trg;
        bulk_g2s(es_u + (unsigned)tid*528u,
                 etab + (size_t)tv*EMB + G*128, 512u, bar);
    } else if (tid < 120) {                // W1 rows (row-major, padded stride)
        int c = tid - 100;
        bulk_g2s(ws_u + (unsigned)c*528u,
                 W1 + (size_t)c*EMB + G*128, 512u, bar);
    }

    // ---- weight precomputes, all during TMA flight (disjoint block slices)
    if (G == 3) {                          // weff = Wfc2 @ Wfc1 (+ bias0)
        if (tid < 10) {
            int k = b*10 + tid;
            if (k < 4840) {
                float w = 0.f;
#pragma unroll
                for (int c = 0; c < 20; c++) w += Wfc2[c]*Wfc1[c*4840 + k];
                g_weff[k] = w;
            }
        } else if (tid == 10 && b == 0) {
            float z = bfc2[0];
#pragma unroll
            for (int c = 0; c < 20; c++) z += Wfc2[c]*bfc1[c];
            g_bias0 = z;
        }
    } else if (G == 2) {                   // Wx | Wy from W2
        if (tid < 10) {
            int q = b*10 + tid;
            if (q < 4800) {
                int sside = q / 2400, r = q % 2400;
                int o = r / 60, rc = r % 60, c = rc / 3, d = rc % 3;
                const float* w = W2 + (o*20 + c)*9;
                g_Wxy[q] = sside ? (w[d*3+0] + w[d*3+1] + w[d*3+2])
                                 : (w[0*3+d] + w[1*3+d] + w[2*3+d]);
            }
        }
    } else if (G == 1 && b == 0) {         // zero BN2 accumulators for this replay
        if (tid < 40) { g_accS[tid] = 0.0; g_accQ[tid] = 0.0; }
    }

    MBAR_WAIT(bar, 0);

    // GEMM: thread = (token-pair tpg, channel-half ch) — verified R11 tile
    const int ch  = tid & 1;
    const int tpg = tid >> 1;
    const bool active = (tpg < 50);
    const int side = (tpg >= 25);
    const int tp   = tpg - side*25;
    const int r1   = tpg + side*25;
    const int r2   = r1 + 25;

    unsigned long long acc2[20];
#pragma unroll
    for (int i = 0; i < 20; i++) acc2[i] = 0ULL;

    if (active) {
        const float4* e1 = (const float4*)esf + r1*33;
        const float4* e2 = (const float4*)esf + r2*33;
        const float4* wf = (const float4*)(smraw + S_OFF_WS);
#pragma unroll
        for (int j4 = 0; j4 < 32; j4++) {
            float4 ea = e1[j4], eb = e2[j4];
            ulonglong2 eva = *reinterpret_cast<ulonglong2*>(&ea);
            ulonglong2 evb = *reinterpret_cast<ulonglong2*>(&eb);
#pragma unroll
            for (int ci = 0; ci < 10; ci++) {
                float4 w = wf[(ch*10 + ci)*33 + j4];
                ulonglong2 wv = *reinterpret_cast<ulonglong2*>(&w);
                ffma2(acc2[ci],      eva.x, wv.x);
                ffma2(acc2[ci],      eva.y, wv.y);
                ffma2(acc2[10 + ci], evb.x, wv.x);
                ffma2(acc2[10 + ci], evb.y, wv.y);
            }
        }
        float* base = &g_fp[((size_t)((G*2 + side)*512 + b))*1000];
        float* d1 = base + tp*20        + ch*10;
        float* d2 = base + (tp + 25)*20 + ch*10;
#pragma unroll
        for (int ci = 0; ci < 10; ci++) {
            unsigned long long v = acc2[ci];
            d1[ci] = __uint_as_float((unsigned)v) + __uint_as_float((unsigned)(v >> 32));
            unsigned long long u = acc2[10 + ci];
            d2[ci] = __uint_as_float((unsigned)u) + __uint_as_float((unsigned)(u >> 32));
        }
    }
}

// ---------------------------------------------------------------------------
// kE: per sample b, BOTH sides — partial sums, BN1 + relu + pool1 + conv1d,
// then BN2 contributions (incl. cross term) via f64 global reductions.
// ---------------------------------------------------------------------------
__global__ __launch_bounds__(128)
void kE(const float* __restrict__ g1, const float* __restrict__ beta1)
{
    __shared__ float fs[2*1050];
    __shared__ float wxy[4800];
    __shared__ float m[2*500];
    __shared__ float bn[160];              // [u][c] scale | [u][c] shift
    __shared__ float shs[80], shq[80];

    const int tid = threadIdx.x;
    const int b   = blockIdx.x;

    // sum the 4 split-K partials, both sides
    for (int q = tid; q < 2000; q += 128) {
        int u = q / 1000, r = q - u*1000;
        float v = 0.f;
#pragma unroll
        for (int g = 0; g < NG; g++)
            v += g_fp[((size_t)((g*2 + u)*512 + b))*1000 + r];
        int t = r / 20, c = r - t*20;
        fs[u*1050 + t*21 + c] = v;
    }
    for (int q = tid; q < 4800; q += 128) wxy[q] = g_Wxy[q];
    __syncthreads();

    // BN1 stats per (side, channel)
    if (tid < 40) {
        int u = tid / 20, c = tid - u*20;
        float s = 0.f, s2 = 0.f;
#pragma unroll 10
        for (int l = 0; l < 50; l++) {
            float v = fs[u*1050 + l*21 + c];
            s += v; s2 += v*v;
        }
        float mu  = s * (1.f/50.f);
        float var = s2 * (1.f/50.f) - mu*mu;
        float sc  = g1[c] * rsqrtf(var + EPSV);
        bn[u*20 + c]      = sc;
        bn[80 + u*20 + c] = beta1[c] - mu*sc;
    }
    __syncthreads();

    // BN1 apply + relu + pool1 -> m[u][c][x]
    for (int q = tid; q < 1000; q += 128) {
        int u = q / 500, r = q - u*500;
        int c = r / 25, x = r - c*25;
        float sc = bn[u*20 + c], sh = bn[80 + u*20 + c];
        float a0 = fs[u*1050 + (2*x    )*21 + c]*sc + sh;
        float a1 = fs[u*1050 + (2*x + 1)*21 + c]*sc + sh;
        m[u*500 + c*25 + x] = fmaxf(fmaxf(a0, a1), 0.f);
    }
    __syncthreads();

    // conv1d, both sides (80 threads), A -> gmem, sums -> smem
    if (tid < 80) {
        int u = tid / 40, o = tid - u*40;
        const float* wb = wxy + u*2400 + o*60;
        const float* mu_ = m + u*500;
        float acc[23];
#pragma unroll
        for (int x = 0; x < 23; x++) acc[x] = 0.f;
#pragma unroll
        for (int c = 0; c < 20; c++) {
            float w0 = wb[c*3], w1 = wb[c*3+1], w2 = wb[c*3+2];
            const float* mm = mu_ + c*25;
#pragma unroll
            for (int x = 0; x < 23; x++)
                acc[x] += w0*mm[x] + w1*mm[x+1] + w2*mm[x+2];
        }
        float s = 0.f, s2 = 0.f;
        float* dst = &g_A[(size_t)(u*BATCH + b)*920 + o*23];
#pragma unroll
        for (int x = 0; x < 23; x++) {
            float v = acc[x];
            dst[x] = v; s += v; s2 += v*v;
        }
        shs[u*40 + o] = s;
        shq[u*40 + o] = s2;
    }
    __syncthreads();

    // BN2 contributions (cross term local — both sides in this block)
    if (tid < 40) {
        double sA = shs[tid],      sB = shs[40 + tid];
        double qA = shq[tid],      qB = shq[40 + tid];
        atomicAdd(&g_accS[tid], 23.0*(sA + sB));
        atomicAdd(&g_accQ[tid], 23.0*qA + 23.0*qB + 2.0*sA*sB);
    }
}

// ---------------------------------------------------------------------------
// kF: BN2 finalize (from 80 doubles, per block) + pool2 + relu + dot + sigmoid
// ---------------------------------------------------------------------------
__global__ __launch_bounds__(256)
void kF(const float* __restrict__ g2, const float* __restrict__ beta2,
        float* __restrict__ out)
{
    __shared__ float ua[440], vb[440], sc_s[40], sh_s[40], red[8];
    const int b = blockIdx.x, tid = threadIdx.x;

    if (tid < 40) {                        // bn2 from accumulators (kE complete)
        double N    = (double)BATCH * 529.0;
        double mean = g_accS[tid] / N;
        double var  = g_accQ[tid] / N - mean*mean;
        float  sc   = g2[tid] * (float)(1.0 / sqrt(var + (double)EPSV));
        sc_s[tid] = sc;
        sh_s[tid] = beta2[tid] - (float)mean * sc;
    }
    __syncthreads();

    for (int q = tid; q < 880; q += 256) {
        int half = (q >= 440);
        int r = q - half*440;
        int o = r / 11, xx = r - o*11;
        float sc = sc_s[o];
        const float* p = &g_A[(size_t)(half*BATCH + b)*920 + o*23];
        (half ? vb : ua)[r] = fmaxf(sc*p[2*xx], sc*p[2*xx+1]);
    }
    __syncthreads();

    float part = 0.f;
    if (tid < 242) {
        const int half = (tid >= 121);
        const int r  = tid - half*121;
        const int yy = r / 11, xx = r - yy*11;
#pragma unroll
        for (int oo = 0; oo < 20; oo++) {
            int o = 2*oo + half;
            part += g_weff[o*121 + r] *
                    fmaxf(ua[o*11 + xx] + vb[o*11 + yy] + sh_s[o], 0.f);
        }
    }
#pragma unroll
    for (int off = 16; off > 0; off >>= 1)
        part += __shfl_down_sync(0xffffffffu, part, off);
    if ((tid & 31) == 0) red[tid >> 5] = part;
    __syncthreads();
    if (tid == 0) {
        float s = 0.f;
#pragma unroll
        for (int w = 0; w < 8; w++) s += red[w];
        out[b] = 1.f / (1.f + expf(-(s + g_bias0)));
    }
}

// ---------------------------------------------------------------------------
extern "C" void kernel_launch(void* const* d_in, const int* in_sizes, int n_in,
                              void* d_out, int out_size)
{
    const int*   src     = (const int*)  d_in[0];
    const int*   trg     = (const int*)  d_in[1];
    const float* emb_src = (const float*)d_in[3];
    const float* emb_trg = (const float*)d_in[4];
    const float* W1      = (const float*)d_in[5];
    const float* g1      = (const float*)d_in[7];
    const float* beta1   = (const float*)d_in[8];
    const float* W2      = (const float*)d_in[9];
    const float* g2      = (const float*)d_in[11];
    const float* beta2   = (const float*)d_in[12];
    const float* Wfc1    = (const float*)d_in[13];
    const float* bfc1    = (const float*)d_in[14];
    const float* Wfc2    = (const float*)d_in[15];
    const float* bfc2    = (const float*)d_in[16];

    cudaFuncSetAttribute(kS, cudaFuncAttributeMaxDynamicSharedMemorySize, SMEM_KS);

    kS<<<dim3(BATCH, NG), 128, SMEM_KS>>>(src, trg, emb_src, emb_trg, W1,
                                          W2, Wfc1, Wfc2, bfc1, bfc2);
    kE<<<BATCH, 128>>>(g1, beta1);
    kF<<<BATCH, 256>>>(g2, beta2, (float*)d_out);
}